// round 2
// baseline (speedup 1.0000x reference)
#include <cuda_runtime.h>
#include <cuda_fp16.h>

#define T_LEN 2048
#define HD    2048
#define G4    8192          // 4*HD
#define NV    128
#define WSZ   (8192ull*2048ull)   // per-layer weight elements
#define REC_CTAS 128

// ---------------- device scratch (static: no runtime allocation) ----------------
__device__ __half g_xh [(size_t)T_LEN*HD];      // x in fp16
__device__ __half g_wih[2*WSZ];                 // W_ih fp16, both layers
__device__ __half g_whh[2*WSZ];                 // W_hh fp16, both layers
__device__ __half g_fcw[(size_t)NV*HD];         // fc_w fp16
__device__ float  g_xg [(size_t)T_LEN*G4];      // precomputed input gates (+bias)
__device__ __half g_h1 [(size_t)T_LEN*HD];      // layer-1 hidden outputs (fp16)
__device__ __half g_h2 [(size_t)T_LEN*HD];      // layer-2 hidden outputs (fp16)
__device__ float  g_hN [2*HD];
__device__ float  g_cN [2*HD];
__device__ __align__(16) __half g_hbuf[2][HD];  // ping-pong h for recurrence
__device__ unsigned          g_cnt;             // barrier arrival counter (monotonic)
__device__ volatile unsigned g_gen;             // barrier generation

// ---------------- fp32 -> fp16 conversion of all big inputs ----------------
__global__ void cvt_inputs(const float* __restrict__ x,
                           const float* __restrict__ wih,
                           const float* __restrict__ whh,
                           const float* __restrict__ fcw) {
    const size_t n = 2*WSZ;
    for (size_t i = (size_t)blockIdx.x*blockDim.x + threadIdx.x; i < n;
         i += (size_t)gridDim.x*blockDim.x) {
        g_wih[i] = __float2half(wih[i]);
        g_whh[i] = __float2half(whh[i]);
        if (i < (size_t)T_LEN*HD) g_xh[i]  = __float2half(x[i]);
        if (i < (size_t)NV*HD)    g_fcw[i] = __float2half(fcw[i]);
    }
}

// ---------------- HMMA GEMM: Xg[M=2048, N=8192] = A[M,K=2048] @ W^T + b ----------------
__device__ __forceinline__ void mma_16816(float d[4], const unsigned a[4], const unsigned b[2]) {
    asm volatile(
        "mma.sync.aligned.m16n8k16.row.col.f32.f16.f16.f32 "
        "{%0,%1,%2,%3}, {%4,%5,%6,%7}, {%8,%9}, {%0,%1,%2,%3};\n"
        : "+f"(d[0]), "+f"(d[1]), "+f"(d[2]), "+f"(d[3])
        : "r"(a[0]), "r"(a[1]), "r"(a[2]), "r"(a[3]), "r"(b[0]), "r"(b[1]));
}

__global__ void __launch_bounds__(256) gemm_ih(int layer,
                                               const float* __restrict__ bih_all,
                                               const float* __restrict__ bhh_all) {
    const __half* A = (layer == 0) ? g_xh : g_h1;          // [2048, 2048] row-major
    const __half* B = g_wih + (size_t)layer*WSZ;           // [8192, 2048] row-major (= col-major K x N)
    const float*  bi = bih_all + layer*G4;
    const float*  bh = bhh_all + layer*G4;

    __shared__ __half As[128][40];
    __shared__ __half Bs[128][40];

    const int tid  = threadIdx.x;
    const int bn   = blockIdx.x * 128;
    const int bm   = blockIdx.y * 128;
    const int warp = tid >> 5, lane = tid & 31;
    const int wm = (warp >> 2) * 64, wn = (warp & 3) * 32;
    const int g = lane >> 2, tq = lane & 3;

    float acc[4][4][4];
    #pragma unroll
    for (int a = 0; a < 4; ++a)
        #pragma unroll
        for (int b = 0; b < 4; ++b)
            #pragma unroll
            for (int c = 0; c < 4; ++c) acc[a][b][c] = 0.f;

    for (int k0 = 0; k0 < HD; k0 += 32) {
        #pragma unroll
        for (int c = 0; c < 2; ++c) {
            int idx = tid + c*256;
            int r = idx >> 2, cc = (idx & 3) * 8;
            *(uint4*)&As[r][cc] = *(const uint4*)(A + (size_t)(bm + r)*HD + k0 + cc);
            *(uint4*)&Bs[r][cc] = *(const uint4*)(B + (size_t)(bn + r)*HD + k0 + cc);
        }
        __syncthreads();
        #pragma unroll
        for (int kk = 0; kk < 32; kk += 16) {
            unsigned af[4][4], bf[4][2];
            #pragma unroll
            for (int mt = 0; mt < 4; ++mt) {
                int r = wm + mt*16 + g;
                af[mt][0] = *(const unsigned*)&As[r  ][kk + 2*tq];
                af[mt][1] = *(const unsigned*)&As[r+8][kk + 2*tq];
                af[mt][2] = *(const unsigned*)&As[r  ][kk + 2*tq + 8];
                af[mt][3] = *(const unsigned*)&As[r+8][kk + 2*tq + 8];
            }
            #pragma unroll
            for (int nt = 0; nt < 4; ++nt) {
                int r = wn + nt*8 + g;
                bf[nt][0] = *(const unsigned*)&Bs[r][kk + 2*tq];
                bf[nt][1] = *(const unsigned*)&Bs[r][kk + 2*tq + 8];
            }
            #pragma unroll
            for (int mt = 0; mt < 4; ++mt)
                #pragma unroll
                for (int nt = 0; nt < 4; ++nt)
                    mma_16816(acc[mt][nt], af[mt], bf[nt]);
        }
        __syncthreads();
    }

    #pragma unroll
    for (int mt = 0; mt < 4; ++mt) {
        #pragma unroll
        for (int nt = 0; nt < 4; ++nt) {
            int row = bm + wm + mt*16 + g;
            int col = bn + wn + nt*8 + 2*tq;
            float b0 = bi[col]   + bh[col];
            float b1 = bi[col+1] + bh[col+1];
            float* Cr  = g_xg + (size_t)row*G4 + col;
            float* Cr8 = Cr + (size_t)8*G4;
            Cr[0]  = acc[mt][nt][0] + b0;
            Cr[1]  = acc[mt][nt][1] + b1;
            Cr8[0] = acc[mt][nt][2] + b0;
            Cr8[1] = acc[mt][nt][3] + b1;
        }
    }
}

// ---------------- recurrence init ----------------
__global__ void init_recur(const float* __restrict__ h0l) {
    int i = blockIdx.x*blockDim.x + threadIdx.x;
    if (i < HD) {
        g_hbuf[0][i] = __float2half(h0l[i]);
        g_hbuf[1][i] = __float2half(0.f);
    }
    if (i == 0) { g_cnt = 0; g_gen = 0; }
}

__device__ __forceinline__ float sigf(float x) { return 1.f / (1.f + __expf(-x)); }

#define DOT8(acc, wv)                                                          \
    do {                                                                       \
        float2 _f;                                                             \
        _f = __half22float2(*(const __half2*)&(wv).x); acc += _f.x*hf0.x + _f.y*hf0.y; \
        _f = __half22float2(*(const __half2*)&(wv).y); acc += _f.x*hf1.x + _f.y*hf1.y; \
        _f = __half22float2(*(const __half2*)&(wv).z); acc += _f.x*hf2.x + _f.y*hf2.y; \
        _f = __half22float2(*(const __half2*)&(wv).w); acc += _f.x*hf3.x + _f.y*hf3.y; \
    } while (0)

// ---------------- persistent LSTM recurrence: 1 warp = 1 hidden unit ----------------
__global__ void __launch_bounds__(512) lstm_recur(int layer, const float* __restrict__ c0all) {
    const __half* Whh  = g_whh + (size_t)layer*WSZ;
    __half*       Hout = layer ? g_h2 : g_h1;

    const int tid  = threadIdx.x;
    const int lane = tid & 31;
    const int wrp  = tid >> 5;
    const int j    = blockIdx.x * 16 + wrp;        // hidden unit 0..2047

    __shared__ __align__(16) __half hs[HD];

    const __half* w0 = Whh + (size_t)j * HD;            // gate i row
    const __half* w1 = w0 + (size_t)HD * HD;            // gate f
    const __half* w2 = w1 + (size_t)HD * HD;            // gate g
    const __half* w3 = w2 + (size_t)HD * HD;            // gate o

    float c = c0all[layer*HD + j];

    for (int t = 0; t < T_LEN; ++t) {
        // stage previous h into smem (L1-bypassing loads: data written by other SMs)
        ((uint2*)hs)[tid] = __ldcg(((const uint2*)g_hbuf[t & 1]) + tid);
        __syncthreads();

        float a0 = 0.f, a1 = 0.f, a2 = 0.f, a3 = 0.f;
        #pragma unroll
        for (int it = 0; it < 8; ++it) {
            const int col = it*256 + lane*8;
            uint4 hv = *(const uint4*)(hs + col);
            uint4 v0 = *(const uint4*)(w0 + col);
            uint4 v1 = *(const uint4*)(w1 + col);
            uint4 v2 = *(const uint4*)(w2 + col);
            uint4 v3 = *(const uint4*)(w3 + col);
            float2 hf0 = __half22float2(*(const __half2*)&hv.x);
            float2 hf1 = __half22float2(*(const __half2*)&hv.y);
            float2 hf2 = __half22float2(*(const __half2*)&hv.z);
            float2 hf3 = __half22float2(*(const __half2*)&hv.w);
            DOT8(a0, v0); DOT8(a1, v1); DOT8(a2, v2); DOT8(a3, v3);
        }
        #pragma unroll
        for (int off = 16; off; off >>= 1) {
            a0 += __shfl_xor_sync(0xffffffffu, a0, off);
            a1 += __shfl_xor_sync(0xffffffffu, a1, off);
            a2 += __shfl_xor_sync(0xffffffffu, a2, off);
            a3 += __shfl_xor_sync(0xffffffffu, a3, off);
        }
        if (lane == 0) {
            const float* xr = g_xg + (size_t)t * G4;
            float ig = sigf (a0 + xr[j]);
            float fg = sigf (a1 + xr[j + 2048]);
            float gg = tanhf(a2 + xr[j + 4096]);
            float og = sigf (a3 + xr[j + 6144]);
            c = fg * c + ig * gg;
            float h = og * tanhf(c);
            __half hh = __float2half(h);
            g_hbuf[(t + 1) & 1][j] = hh;
            Hout[(size_t)t * HD + j] = hh;
            if (t == T_LEN - 1) { g_hN[layer*HD + j] = h; g_cN[layer*HD + j] = c; }
        }
        __threadfence();      // publish h writes (device scope) before arriving
        __syncthreads();      // all warps of this CTA done + fenced

        if (tid == 0) {
            unsigned arrived = atomicAdd(&g_cnt, 1u) + 1u;
            unsigned target  = (unsigned)gridDim.x * (unsigned)(t + 1);
            if (arrived == target) {
                g_gen = (unsigned)(t + 1);           // publish generation
            } else {
                while (g_gen < (unsigned)(t + 1)) { __nanosleep(32); }
            }
            __threadfence();  // acquire before next step's reads
        }
        __syncthreads();
    }
}

// ---------------- FC + log_softmax: one CTA per timestep ----------------
__global__ void __launch_bounds__(128) fc_logsoftmax(const float* __restrict__ fcb,
                                                     float* __restrict__ out) {
    const int t = blockIdx.x, v = threadIdx.x;
    __shared__ __align__(16) __half hs[HD];
    __shared__ float lg[NV];
    __shared__ float red[NV];

    const uint4* src = (const uint4*)(g_h2 + (size_t)t * HD);
    ((uint4*)hs)[v]       = src[v];
    ((uint4*)hs)[v + 128] = src[v + 128];
    __syncthreads();

    float acc = fcb[v];
    const __half* wr = g_fcw + (size_t)v * HD;
    #pragma unroll 4
    for (int k = 0; k < HD; k += 8) {
        uint4 wv = *(const uint4*)(wr + k);
        uint4 hv = *(const uint4*)(hs + k);
        float2 a, b;
        a = __half22float2(*(const __half2*)&wv.x); b = __half22float2(*(const __half2*)&hv.x); acc += a.x*b.x + a.y*b.y;
        a = __half22float2(*(const __half2*)&wv.y); b = __half22float2(*(const __half2*)&hv.y); acc += a.x*b.x + a.y*b.y;
        a = __half22float2(*(const __half2*)&wv.z); b = __half22float2(*(const __half2*)&hv.z); acc += a.x*b.x + a.y*b.y;
        a = __half22float2(*(const __half2*)&wv.w); b = __half22float2(*(const __half2*)&hv.w); acc += a.x*b.x + a.y*b.y;
    }
    lg[v] = acc; red[v] = acc;
    __syncthreads();
    for (int s = 64; s > 0; s >>= 1) { if (v < s) red[v] = fmaxf(red[v], red[v + s]); __syncthreads(); }
    float mx = red[0];
    __syncthreads();
    red[v] = __expf(lg[v] - mx);
    __syncthreads();
    for (int s = 64; s > 0; s >>= 1) { if (v < s) red[v] += red[v + s]; __syncthreads(); }
    float lse = mx + logf(red[0]);
    out[(size_t)t * NV + v] = lg[v] - lse;
}

// ---------------- optional h_n / c_n tail ----------------
__global__ void write_states(float* __restrict__ out) {
    int i = blockIdx.x*blockDim.x + threadIdx.x;
    if (i < 2*HD) {
        out[(size_t)T_LEN*NV + i]          = g_hN[i];
        out[(size_t)T_LEN*NV + 2*HD + i]   = g_cN[i];
    }
}

// ---------------- launcher ----------------
extern "C" void kernel_launch(void* const* d_in, const int* in_sizes, int n_in,
                              void* d_out, int out_size) {
    const float* x   = (const float*)d_in[0];
    const float* h0  = (const float*)d_in[1];
    const float* c0  = (const float*)d_in[2];
    const float* Wih = (const float*)d_in[3];   // converted in cvt_inputs
    const float* Whh = (const float*)d_in[4];
    const float* bih = (const float*)d_in[5];
    const float* bhh = (const float*)d_in[6];
    const float* fcw = (const float*)d_in[7];
    const float* fcb = (const float*)d_in[8];
    float* out = (float*)d_out;
    (void)in_sizes; (void)n_in;

    cvt_inputs<<<2048, 256>>>(x, Wih, Whh, fcw);

    dim3 ggrid(G4/128, T_LEN/128);
    for (int l = 0; l < 2; ++l) {
        gemm_ih<<<ggrid, 256>>>(l, bih, bhh);
        init_recur<<<8, 256>>>(h0 + l*HD);
        lstm_recur<<<REC_CTAS, 512>>>(l, c0);
    }

    fc_logsoftmax<<<T_LEN, 128>>>(fcb, out);

    if (out_size >= T_LEN*NV + 4*HD)
        write_states<<<(2*HD + 255)/256, 256>>>(out);
}

// round 4
// speedup vs baseline: 1.1046x; 1.1046x over previous
#include <cuda_runtime.h>
#include <cuda_fp16.h>

#define T_LEN 2048
#define HD    2048
#define G4    8192
#define NV    128
#define WSZ   (8192ull*2048ull)
#define REC_CTAS 148
#define UNITS_SM 13                       // units resident in smem per CTA
#define SMEM_REC ((UNITS_SM*4*HD + HD) * 2)   // weights + h stage, bytes

// ---------------- device scratch ----------------
__device__ __half g_xh [(size_t)T_LEN*HD];
__device__ __half g_wih[2*WSZ];
__device__ __half g_whh[2*WSZ];
__device__ __half g_fcw[(size_t)NV*HD];
__device__ float  g_xg [(size_t)T_LEN*G4];
__device__ __half g_h1 [(size_t)T_LEN*HD];
__device__ __half g_h2 [(size_t)T_LEN*HD];
__device__ float  g_hN [2*HD];
__device__ float  g_cN [2*HD];
__device__ __align__(16) __half g_h0h[HD];   // fp16 h0 for current layer
__device__ unsigned          g_cnt;
__device__ volatile unsigned g_gen;

// ---------------- fp32 -> fp16 conversion ----------------
__global__ void cvt_inputs(const float* __restrict__ x,
                           const float* __restrict__ wih,
                           const float* __restrict__ whh,
                           const float* __restrict__ fcw) {
    const size_t n = 2*WSZ;
    for (size_t i = (size_t)blockIdx.x*blockDim.x + threadIdx.x; i < n;
         i += (size_t)gridDim.x*blockDim.x) {
        g_wih[i] = __float2half(wih[i]);
        g_whh[i] = __float2half(whh[i]);
        if (i < (size_t)T_LEN*HD) g_xh[i]  = __float2half(x[i]);
        if (i < (size_t)NV*HD)    g_fcw[i] = __float2half(fcw[i]);
    }
}

// ---------------- HMMA GEMM: Xg = A @ W_ih^T + (b_ih + b_hh) ----------------
__device__ __forceinline__ void mma_16816(float d[4], const unsigned a[4], const unsigned b[2]) {
    asm volatile(
        "mma.sync.aligned.m16n8k16.row.col.f32.f16.f16.f32 "
        "{%0,%1,%2,%3}, {%4,%5,%6,%7}, {%8,%9}, {%0,%1,%2,%3};\n"
        : "+f"(d[0]), "+f"(d[1]), "+f"(d[2]), "+f"(d[3])
        : "r"(a[0]), "r"(a[1]), "r"(a[2]), "r"(a[3]), "r"(b[0]), "r"(b[1]));
}

__global__ void __launch_bounds__(256) gemm_ih(int layer,
                                               const float* __restrict__ bih_all,
                                               const float* __restrict__ bhh_all) {
    const __half* A = (layer == 0) ? g_xh : g_h1;
    const __half* B = g_wih + (size_t)layer*WSZ;
    const float*  bi = bih_all + layer*G4;
    const float*  bh = bhh_all + layer*G4;

    __shared__ __half As[128][40];
    __shared__ __half Bs[128][40];

    const int tid  = threadIdx.x;
    const int bn   = blockIdx.x * 128;
    const int bm   = blockIdx.y * 128;
    const int warp = tid >> 5, lane = tid & 31;
    const int wm = (warp >> 2) * 64, wn = (warp & 3) * 32;
    const int g = lane >> 2, tq = lane & 3;

    float acc[4][4][4];
    #pragma unroll
    for (int a = 0; a < 4; ++a)
        #pragma unroll
        for (int b = 0; b < 4; ++b)
            #pragma unroll
            for (int c = 0; c < 4; ++c) acc[a][b][c] = 0.f;

    for (int k0 = 0; k0 < HD; k0 += 32) {
        #pragma unroll
        for (int c = 0; c < 2; ++c) {
            int idx = tid + c*256;
            int r = idx >> 2, cc = (idx & 3) * 8;
            *(uint4*)&As[r][cc] = *(const uint4*)(A + (size_t)(bm + r)*HD + k0 + cc);
            *(uint4*)&Bs[r][cc] = *(const uint4*)(B + (size_t)(bn + r)*HD + k0 + cc);
        }
        __syncthreads();
        #pragma unroll
        for (int kk = 0; kk < 32; kk += 16) {
            unsigned af[4][4], bf[4][2];
            #pragma unroll
            for (int mt = 0; mt < 4; ++mt) {
                int r = wm + mt*16 + g;
                af[mt][0] = *(const unsigned*)&As[r  ][kk + 2*tq];
                af[mt][1] = *(const unsigned*)&As[r+8][kk + 2*tq];
                af[mt][2] = *(const unsigned*)&As[r  ][kk + 2*tq + 8];
                af[mt][3] = *(const unsigned*)&As[r+8][kk + 2*tq + 8];
            }
            #pragma unroll
            for (int nt = 0; nt < 4; ++nt) {
                int r = wn + nt*8 + g;
                bf[nt][0] = *(const unsigned*)&Bs[r][kk + 2*tq];
                bf[nt][1] = *(const unsigned*)&Bs[r][kk + 2*tq + 8];
            }
            #pragma unroll
            for (int mt = 0; mt < 4; ++mt)
                #pragma unroll
                for (int nt = 0; nt < 4; ++nt)
                    mma_16816(acc[mt][nt], af[mt], bf[nt]);
        }
        __syncthreads();
    }

    #pragma unroll
    for (int mt = 0; mt < 4; ++mt) {
        #pragma unroll
        for (int nt = 0; nt < 4; ++nt) {
            int row = bm + wm + mt*16 + g;
            int col = bn + wn + nt*8 + 2*tq;
            float b0 = bi[col]   + bh[col];
            float b1 = bi[col+1] + bh[col+1];
            float* Cr  = g_xg + (size_t)row*G4 + col;
            float* Cr8 = Cr + (size_t)8*G4;
            Cr[0]  = acc[mt][nt][0] + b0;
            Cr[1]  = acc[mt][nt][1] + b1;
            Cr8[0] = acc[mt][nt][2] + b0;
            Cr8[1] = acc[mt][nt][3] + b1;
        }
    }
}

// ---------------- recurrence init ----------------
__global__ void init_recur(const float* __restrict__ h0l) {
    int i = blockIdx.x*blockDim.x + threadIdx.x;
    if (i < HD) g_h0h[i] = __float2half(h0l[i]);
    if (i == 0) { g_cnt = 0; g_gen = 0; }
}

__device__ __forceinline__ float sigf(float x) { return 1.f / (1.f + __expf(-x)); }

#define DOT8(acc, wv)                                                          \
    do {                                                                       \
        float2 _f;                                                             \
        _f = __half22float2(*(const __half2*)&(wv).x); acc += _f.x*hf0.x + _f.y*hf0.y; \
        _f = __half22float2(*(const __half2*)&(wv).y); acc += _f.x*hf1.x + _f.y*hf1.y; \
        _f = __half22float2(*(const __half2*)&(wv).z); acc += _f.x*hf2.x + _f.y*hf2.y; \
        _f = __half22float2(*(const __half2*)&(wv).w); acc += _f.x*hf3.x + _f.y*hf3.y; \
    } while (0)

#define COMPUTE_DOTS(W0, W1, W2, W3)                                           \
    do {                                                                       \
        a0 = a1 = a2 = a3 = 0.f;                                               \
        _Pragma("unroll")                                                      \
        for (int it = 0; it < 8; ++it) {                                       \
            const int col = it*256 + lane*8;                                   \
            uint4 hv = *(const uint4*)(hs + col);                              \
            uint4 v0 = *(const uint4*)((W0) + col);                            \
            uint4 v1 = *(const uint4*)((W1) + col);                            \
            uint4 v2 = *(const uint4*)((W2) + col);                            \
            uint4 v3 = *(const uint4*)((W3) + col);                            \
            float2 hf0 = __half22float2(*(const __half2*)&hv.x);               \
            float2 hf1 = __half22float2(*(const __half2*)&hv.y);               \
            float2 hf2 = __half22float2(*(const __half2*)&hv.z);               \
            float2 hf3 = __half22float2(*(const __half2*)&hv.w);               \
            DOT8(a0, v0); DOT8(a1, v1); DOT8(a2, v2); DOT8(a3, v3);            \
        }                                                                      \
    } while (0)

// ---------------- persistent weight-stationary LSTM recurrence ----------------
// 148 CTAs; CTA b owns units [start, start+nb) with nb = 14 (b<124) or 13.
// Warps 0..12 compute from SMEM-resident weights; warp 13 (if present)
// streams its 16KB of weights from L2 each step.
__global__ void __launch_bounds__(448) lstm_recur(int layer, const float* __restrict__ c0all) {
    extern __shared__ __half sm[];
    __half* ws = sm;                        // UNITS_SM * 4 * HD halfs
    __half* hs = sm + UNITS_SM*4*HD;        // HD halfs

    const int tid  = threadIdx.x;
    const int lane = tid & 31;
    const int wrp  = tid >> 5;
    const int b    = blockIdx.x;
    const int nb   = (b < 124) ? 14 : 13;
    const int start = b*13 + min(b, 124);
    const int j    = start + wrp;
    const bool valid = (wrp < nb);

    const __half* Whh  = g_whh + (size_t)layer*WSZ;
    __half*       Hout = layer ? g_h2 : g_h1;

    // Stage the 13 smem-resident units' weights (once per layer launch).
    {
        const int total = UNITS_SM*4*HD/8;   // 13312 uint4
        for (int idx = tid; idx < total; idx += 448) {
            int u   = idx >> 10;             // / 1024
            int rem = idx & 1023;
            int g   = rem >> 8;
            int k   = (rem & 255) << 3;
            *(uint4*)(ws + ((size_t)(u*4 + g))*HD + k) =
                *(const uint4*)(Whh + (size_t)g*HD*HD + (size_t)(start + u)*HD + k);
        }
    }

    float c = valid ? c0all[layer*HD + j] : 0.f;

    // Global-streaming pointers for the 14th unit.
    const __half* gw0 = Whh + (size_t)j*HD;
    const __half* gw1 = gw0 + (size_t)HD*HD;
    const __half* gw2 = gw1 + (size_t)HD*HD;
    const __half* gw3 = gw2 + (size_t)HD*HD;

    __syncthreads();

    for (int t = 0; t < T_LEN; ++t) {
        // stage h_{t-1} into smem: HD halfs = 256 uint4 (fresh addresses each step)
        const __half* hsrc = (t == 0) ? g_h0h : (Hout + (size_t)(t-1)*HD);
        if (tid < 256) ((uint4*)hs)[tid] = ((const uint4*)hsrc)[tid];
        __syncthreads();

        float a0, a1, a2, a3;
        if (valid) {
            if (wrp < UNITS_SM) {
                const __half* w0 = ws + (size_t)(wrp*4)*HD;
                const __half* w1 = w0 + HD;
                const __half* w2 = w1 + HD;
                const __half* w3 = w2 + HD;
                COMPUTE_DOTS(w0, w1, w2, w3);
            } else {
                COMPUTE_DOTS(gw0, gw1, gw2, gw3);
            }
            #pragma unroll
            for (int off = 16; off; off >>= 1) {
                a0 += __shfl_xor_sync(0xffffffffu, a0, off);
                a1 += __shfl_xor_sync(0xffffffffu, a1, off);
                a2 += __shfl_xor_sync(0xffffffffu, a2, off);
                a3 += __shfl_xor_sync(0xffffffffu, a3, off);
            }
            if (lane == 0) {
                const float* xr = g_xg + (size_t)t * G4;
                float ig = sigf (a0 + xr[j]);
                float fg = sigf (a1 + xr[j + 2048]);
                float gg = tanhf(a2 + xr[j + 4096]);
                float og = sigf (a3 + xr[j + 6144]);
                c = fg * c + ig * gg;
                float h = og * tanhf(c);
                Hout[(size_t)t * HD + j] = __float2half(h);
                if (t == T_LEN - 1) { g_hN[layer*HD + j] = h; g_cN[layer*HD + j] = c; }
            }
        }

        __threadfence();
        __syncthreads();
        if (tid == 0) {
            unsigned arrived = atomicAdd(&g_cnt, 1u) + 1u;
            unsigned target  = (unsigned)gridDim.x * (unsigned)(t + 1);
            if (arrived == target) {
                g_gen = (unsigned)(t + 1);
            } else {
                while (g_gen < (unsigned)(t + 1)) { __nanosleep(32); }
            }
            __threadfence();
        }
        __syncthreads();
    }
}

// ---------------- FC + log_softmax: one CTA per timestep ----------------
__global__ void __launch_bounds__(128) fc_logsoftmax(const float* __restrict__ fcb,
                                                     float* __restrict__ out) {
    const int t = blockIdx.x, v = threadIdx.x;
    __shared__ __align__(16) __half hsl[HD];
    __shared__ float lg[NV];
    __shared__ float red[NV];

    const uint4* src = (const uint4*)(g_h2 + (size_t)t * HD);
    ((uint4*)hsl)[v]       = src[v];
    ((uint4*)hsl)[v + 128] = src[v + 128];
    __syncthreads();

    float acc = fcb[v];
    const __half* wr = g_fcw + (size_t)v * HD;
    #pragma unroll 4
    for (int k = 0; k < HD; k += 8) {
        uint4 wv = *(const uint4*)(wr + k);
        uint4 hv = *(const uint4*)(hsl + k);
        float2 a, bb;
        a = __half22float2(*(const __half2*)&wv.x); bb = __half22float2(*(const __half2*)&hv.x); acc += a.x*bb.x + a.y*bb.y;
        a = __half22float2(*(const __half2*)&wv.y); bb = __half22float2(*(const __half2*)&hv.y); acc += a.x*bb.x + a.y*bb.y;
        a = __half22float2(*(const __half2*)&wv.z); bb = __half22float2(*(const __half2*)&hv.z); acc += a.x*bb.x + a.y*bb.y;
        a = __half22float2(*(const __half2*)&wv.w); bb = __half22float2(*(const __half2*)&hv.w); acc += a.x*bb.x + a.y*bb.y;
    }
    lg[v] = acc; red[v] = acc;
    __syncthreads();
    for (int s = 64; s > 0; s >>= 1) { if (v < s) red[v] = fmaxf(red[v], red[v + s]); __syncthreads(); }
    float mx = red[0];
    __syncthreads();
    red[v] = __expf(lg[v] - mx);
    __syncthreads();
    for (int s = 64; s > 0; s >>= 1) { if (v < s) red[v] += red[v + s]; __syncthreads(); }
    float lse = mx + logf(red[0]);
    out[(size_t)t * NV + v] = lg[v] - lse;
}

// ---------------- optional h_n / c_n tail ----------------
__global__ void write_states(float* __restrict__ out) {
    int i = blockIdx.x*blockDim.x + threadIdx.x;
    if (i < 2*HD) {
        out[(size_t)T_LEN*NV + i]        = g_hN[i];
        out[(size_t)T_LEN*NV + 2*HD + i] = g_cN[i];
    }
}

// ---------------- launcher ----------------
extern "C" void kernel_launch(void* const* d_in, const int* in_sizes, int n_in,
                              void* d_out, int out_size) {
    const float* x   = (const float*)d_in[0];
    const float* h0  = (const float*)d_in[1];
    const float* c0  = (const float*)d_in[2];
    const float* Wih = (const float*)d_in[3];
    const float* Whh = (const float*)d_in[4];
    const float* bih = (const float*)d_in[5];
    const float* bhh = (const float*)d_in[6];
    const float* fcw = (const float*)d_in[7];
    const float* fcb = (const float*)d_in[8];
    float* out = (float*)d_out;
    (void)in_sizes; (void)n_in;

    cudaFuncSetAttribute(lstm_recur, cudaFuncAttributeMaxDynamicSharedMemorySize, SMEM_REC);

    cvt_inputs<<<2048, 256>>>(x, Wih, Whh, fcw);

    dim3 ggrid(G4/128, T_LEN/128);
    for (int l = 0; l < 2; ++l) {
        gemm_ih<<<ggrid, 256>>>(l, bih, bhh);
        init_recur<<<8, 256>>>(h0 + l*HD);
        lstm_recur<<<REC_CTAS, 448, SMEM_REC>>>(l, c0);
    }

    fc_logsoftmax<<<T_LEN, 128>>>(fcb, out);

    if (out_size >= T_LEN*NV + 4*HD)
        write_states<<<(2*HD + 255)/256, 256>>>(out);
}

// round 5
// speedup vs baseline: 1.2466x; 1.1285x over previous
#include <cuda_runtime.h>
#include <cuda_fp16.h>

#define T_LEN 2048
#define HD    2048
#define G4    8192
#define NV    128
#define WSZ   (8192ull*2048ull)
#define REC_CTAS 148
#define UNITS_SM 13
#define SMEM_REC ((UNITS_SM*4*HD + HD) * 2)

// ---------------- device scratch ----------------
__device__ __half g_xh [(size_t)T_LEN*HD];
__device__ __half g_wih[2*WSZ];
__device__ __half g_whh[2*WSZ];
__device__ __half g_fcw[(size_t)NV*HD];
__device__ float  g_xg [(size_t)T_LEN*G4];   // layout [t][j][gate] (gate-interleaved)
__device__ __half g_h1 [(size_t)T_LEN*HD];
__device__ __half g_h2 [(size_t)T_LEN*HD];
__device__ float  g_hN [2*HD];
__device__ float  g_cN [2*HD];
__device__ __align__(16) __half g_h0h[HD];
__device__ unsigned          g_cnt;
__device__ volatile unsigned g_gen;

// ---------------- fp32 -> fp16 conversion ----------------
__global__ void cvt_inputs(const float* __restrict__ x,
                           const float* __restrict__ wih,
                           const float* __restrict__ whh,
                           const float* __restrict__ fcw) {
    const size_t n = 2*WSZ;
    for (size_t i = (size_t)blockIdx.x*blockDim.x + threadIdx.x; i < n;
         i += (size_t)gridDim.x*blockDim.x) {
        g_wih[i] = __float2half(wih[i]);
        g_whh[i] = __float2half(whh[i]);
        if (i < (size_t)T_LEN*HD) g_xh[i]  = __float2half(x[i]);
        if (i < (size_t)NV*HD)    g_fcw[i] = __float2half(fcw[i]);
    }
}

// ---------------- HMMA GEMM: Xg = A @ W_ih^T + (b_ih + b_hh) ----------------
__device__ __forceinline__ void mma_16816(float d[4], const unsigned a[4], const unsigned b[2]) {
    asm volatile(
        "mma.sync.aligned.m16n8k16.row.col.f32.f16.f16.f32 "
        "{%0,%1,%2,%3}, {%4,%5,%6,%7}, {%8,%9}, {%0,%1,%2,%3};\n"
        : "+f"(d[0]), "+f"(d[1]), "+f"(d[2]), "+f"(d[3])
        : "r"(a[0]), "r"(a[1]), "r"(a[2]), "r"(a[3]), "r"(b[0]), "r"(b[1]));
}

__global__ void __launch_bounds__(256) gemm_ih(int layer,
                                               const float* __restrict__ bih_all,
                                               const float* __restrict__ bhh_all) {
    const __half* A = (layer == 0) ? g_xh : g_h1;
    const __half* B = g_wih + (size_t)layer*WSZ;
    const float*  bi = bih_all + layer*G4;
    const float*  bh = bhh_all + layer*G4;

    __shared__ __half As[128][40];
    __shared__ __half Bs[128][40];

    const int tid  = threadIdx.x;
    const int bn   = blockIdx.x * 128;
    const int bm   = blockIdx.y * 128;
    const int warp = tid >> 5, lane = tid & 31;
    const int wm = (warp >> 2) * 64, wn = (warp & 3) * 32;
    const int g = lane >> 2, tq = lane & 3;

    float acc[4][4][4];
    #pragma unroll
    for (int a = 0; a < 4; ++a)
        #pragma unroll
        for (int b = 0; b < 4; ++b)
            #pragma unroll
            for (int c = 0; c < 4; ++c) acc[a][b][c] = 0.f;

    for (int k0 = 0; k0 < HD; k0 += 32) {
        #pragma unroll
        for (int c = 0; c < 2; ++c) {
            int idx = tid + c*256;
            int r = idx >> 2, cc = (idx & 3) * 8;
            *(uint4*)&As[r][cc] = *(const uint4*)(A + (size_t)(bm + r)*HD + k0 + cc);
            *(uint4*)&Bs[r][cc] = *(const uint4*)(B + (size_t)(bn + r)*HD + k0 + cc);
        }
        __syncthreads();
        #pragma unroll
        for (int kk = 0; kk < 32; kk += 16) {
            unsigned af[4][4], bf[4][2];
            #pragma unroll
            for (int mt = 0; mt < 4; ++mt) {
                int r = wm + mt*16 + g;
                af[mt][0] = *(const unsigned*)&As[r  ][kk + 2*tq];
                af[mt][1] = *(const unsigned*)&As[r+8][kk + 2*tq];
                af[mt][2] = *(const unsigned*)&As[r  ][kk + 2*tq + 8];
                af[mt][3] = *(const unsigned*)&As[r+8][kk + 2*tq + 8];
            }
            #pragma unroll
            for (int nt = 0; nt < 4; ++nt) {
                int r = wn + nt*8 + g;
                bf[nt][0] = *(const unsigned*)&Bs[r][kk + 2*tq];
                bf[nt][1] = *(const unsigned*)&Bs[r][kk + 2*tq + 8];
            }
            #pragma unroll
            for (int mt = 0; mt < 4; ++mt)
                #pragma unroll
                for (int nt = 0; nt < 4; ++nt)
                    mma_16816(acc[mt][nt], af[mt], bf[nt]);
        }
        __syncthreads();
    }

    // Epilogue writes gate-interleaved layout: g_xg[row*G4 + j*4 + gate]
    #pragma unroll
    for (int mt = 0; mt < 4; ++mt) {
        #pragma unroll
        for (int nt = 0; nt < 4; ++nt) {
            int row = bm + wm + mt*16 + g;
            int col = bn + wn + nt*8 + 2*tq;
            int gate = col >> 11;
            int j    = col & 2047;
            float b0 = bi[col]   + bh[col];
            float b1 = bi[col+1] + bh[col+1];
            size_t i0  = (size_t)row*G4 + ((size_t)j << 2) + gate;
            size_t i08 = i0 + (size_t)8*G4;
            g_xg[i0]      = acc[mt][nt][0] + b0;
            g_xg[i0 + 4]  = acc[mt][nt][1] + b1;
            g_xg[i08]     = acc[mt][nt][2] + b0;
            g_xg[i08 + 4] = acc[mt][nt][3] + b1;
        }
    }
}

// ---------------- recurrence init ----------------
__global__ void init_recur(const float* __restrict__ h0l) {
    int i = blockIdx.x*blockDim.x + threadIdx.x;
    if (i < HD) g_h0h[i] = __float2half(h0l[i]);
    if (i == 0) { g_cnt = 0; g_gen = 0; }
}

__device__ __forceinline__ float sigf(float x) { return 1.f / (1.f + __expf(-x)); }

__device__ __forceinline__ float hsum4(const __half2 s[4]) {
    float2 f0 = __half22float2(s[0]);
    float2 f1 = __half22float2(s[1]);
    float2 f2 = __half22float2(s[2]);
    float2 f3 = __half22float2(s[3]);
    return ((f0.x + f0.y) + (f1.x + f1.y)) + ((f2.x + f2.y) + (f3.x + f3.y));
}

// HFMA2 dot: 16 independent half2 accumulator chains (4 per gate)
#define COMPUTE_DOTS_H2(W0, W1, W2, W3)                                        \
    do {                                                                       \
        _Pragma("unroll")                                                      \
        for (int k = 0; k < 4; ++k) { s0[k] = z; s1[k] = z; s2[k] = z; s3[k] = z; } \
        _Pragma("unroll")                                                      \
        for (int it = 0; it < 8; ++it) {                                       \
            const int col = it*256 + lane*8;                                   \
            uint4 hv = *(const uint4*)(hs + col);                              \
            uint4 v0 = *(const uint4*)((W0) + col);                            \
            uint4 v1 = *(const uint4*)((W1) + col);                            \
            uint4 v2 = *(const uint4*)((W2) + col);                            \
            uint4 v3 = *(const uint4*)((W3) + col);                            \
            const __half2* hp = (const __half2*)&hv;                           \
            const __half2* p0 = (const __half2*)&v0;                           \
            const __half2* p1 = (const __half2*)&v1;                           \
            const __half2* p2 = (const __half2*)&v2;                           \
            const __half2* p3 = (const __half2*)&v3;                           \
            _Pragma("unroll")                                                  \
            for (int k = 0; k < 4; ++k) {                                      \
                s0[k] = __hfma2(p0[k], hp[k], s0[k]);                          \
                s1[k] = __hfma2(p1[k], hp[k], s1[k]);                          \
                s2[k] = __hfma2(p2[k], hp[k], s2[k]);                          \
                s3[k] = __hfma2(p3[k], hp[k], s3[k]);                          \
            }                                                                  \
        }                                                                      \
    } while (0)

// ---------------- persistent weight-stationary LSTM recurrence ----------------
__global__ void __launch_bounds__(448) lstm_recur(int layer, const float* __restrict__ c0all) {
    extern __shared__ __half sm[];
    __half* ws = sm;                        // UNITS_SM * 4 * HD halfs
    __half* hs = sm + UNITS_SM*4*HD;        // HD halfs

    const int tid  = threadIdx.x;
    const int lane = tid & 31;
    const int wrp  = tid >> 5;
    const int b    = blockIdx.x;
    const int nb   = (b < 124) ? 14 : 13;
    const int start = b*13 + min(b, 124);
    const int j    = start + wrp;
    const bool valid = (wrp < nb);

    const __half* Whh  = g_whh + (size_t)layer*WSZ;
    __half*       Hout = layer ? g_h2 : g_h1;

    // Stage the 13 smem-resident units' weights once.
    {
        const int total = UNITS_SM*4*HD/8;
        for (int idx = tid; idx < total; idx += 448) {
            int u   = idx >> 10;
            int rem = idx & 1023;
            int g   = rem >> 8;
            int k   = (rem & 255) << 3;
            *(uint4*)(ws + ((size_t)(u*4 + g))*HD + k) =
                *(const uint4*)(Whh + (size_t)g*HD*HD + (size_t)(start + u)*HD + k);
        }
    }

    float c = valid ? c0all[layer*HD + j] : 0.f;

    const __half* gw0 = Whh + (size_t)j*HD;
    const __half* gw1 = gw0 + (size_t)HD*HD;
    const __half* gw2 = gw1 + (size_t)HD*HD;
    const __half* gw3 = gw2 + (size_t)HD*HD;

    __syncthreads();

    const __half2 z = __float2half2_rn(0.f);

    for (int t = 0; t < T_LEN; ++t) {
        // Prefetch this unit's 4 input-gate values (hidden behind the dot).
        float4 xv = make_float4(0.f, 0.f, 0.f, 0.f);
        if (valid && lane == 0)
            xv = __ldcg(((const float4*)(g_xg + (size_t)t*G4)) + j);

        // Stage h_{t-1} into smem: 256 uint4.
        const __half* hsrc = (t == 0) ? g_h0h : (Hout + (size_t)(t-1)*HD);
        if (tid < 256) ((uint4*)hs)[tid] = ((const uint4*)hsrc)[tid];
        __syncthreads();

        __half2 s0[4], s1[4], s2[4], s3[4];
        if (valid) {
            if (wrp < UNITS_SM) {
                const __half* w0 = ws + (size_t)(wrp*4)*HD;
                COMPUTE_DOTS_H2(w0, w0 + HD, w0 + 2*HD, w0 + 3*HD);
            } else {
                COMPUTE_DOTS_H2(gw0, gw1, gw2, gw3);
            }
            float a0 = hsum4(s0), a1 = hsum4(s1), a2 = hsum4(s2), a3 = hsum4(s3);
            #pragma unroll
            for (int off = 16; off; off >>= 1) {
                a0 += __shfl_xor_sync(0xffffffffu, a0, off);
                a1 += __shfl_xor_sync(0xffffffffu, a1, off);
                a2 += __shfl_xor_sync(0xffffffffu, a2, off);
                a3 += __shfl_xor_sync(0xffffffffu, a3, off);
            }
            if (lane == 0) {
                float ig = sigf (a0 + xv.x);
                float fg = sigf (a1 + xv.y);
                float gg = tanhf(a2 + xv.z);
                float og = sigf (a3 + xv.w);
                c = fg * c + ig * gg;
                float h = og * tanhf(c);
                Hout[(size_t)t * HD + j] = __float2half(h);
                if (t == T_LEN - 1) { g_hN[layer*HD + j] = h; g_cN[layer*HD + j] = c; }
                __threadfence();   // writers only: publish before barrier arrive
            }
        }

        __syncthreads();
        if (tid == 0) {
            unsigned arrived = atomicAdd(&g_cnt, 1u) + 1u;
            unsigned target  = (unsigned)gridDim.x * (unsigned)(t + 1);
            if (arrived == target) {
                __threadfence();
                g_gen = (unsigned)(t + 1);
            } else {
                while (g_gen < (unsigned)(t + 1)) {}
            }
            __threadfence();
        }
        __syncthreads();
    }
}

// ---------------- FC + log_softmax: one CTA per timestep ----------------
__global__ void __launch_bounds__(128) fc_logsoftmax(const float* __restrict__ fcb,
                                                     float* __restrict__ out) {
    const int t = blockIdx.x, v = threadIdx.x;
    __shared__ __align__(16) __half hsl[HD];
    __shared__ float lg[NV];
    __shared__ float red[NV];

    const uint4* src = (const uint4*)(g_h2 + (size_t)t * HD);
    ((uint4*)hsl)[v]       = src[v];
    ((uint4*)hsl)[v + 128] = src[v + 128];
    __syncthreads();

    float acc = fcb[v];
    const __half* wr = g_fcw + (size_t)v * HD;
    #pragma unroll 4
    for (int k = 0; k < HD; k += 8) {
        uint4 wv = *(const uint4*)(wr + k);
        uint4 hv = *(const uint4*)(hsl + k);
        float2 a, bb;
        a = __half22float2(*(const __half2*)&wv.x); bb = __half22float2(*(const __half2*)&hv.x); acc += a.x*bb.x + a.y*bb.y;
        a = __half22float2(*(const __half2*)&wv.y); bb = __half22float2(*(const __half2*)&hv.y); acc += a.x*bb.x + a.y*bb.y;
        a = __half22float2(*(const __half2*)&wv.z); bb = __half22float2(*(const __half2*)&hv.z); acc += a.x*bb.x + a.y*bb.y;
        a = __half22float2(*(const __half2*)&wv.w); bb = __half22float2(*(const __half2*)&hv.w); acc += a.x*bb.x + a.y*bb.y;
    }
    lg[v] = acc; red[v] = acc;
    __syncthreads();
    for (int s = 64; s > 0; s >>= 1) { if (v < s) red[v] = fmaxf(red[v], red[v + s]); __syncthreads(); }
    float mx = red[0];
    __syncthreads();
    red[v] = __expf(lg[v] - mx);
    __syncthreads();
    for (int s = 64; s > 0; s >>= 1) { if (v < s) red[v] += red[v + s]; __syncthreads(); }
    float lse = mx + logf(red[0]);
    out[(size_t)t * NV + v] = lg[v] - lse;
}

// ---------------- optional h_n / c_n tail ----------------
__global__ void write_states(float* __restrict__ out) {
    int i = blockIdx.x*blockDim.x + threadIdx.x;
    if (i < 2*HD) {
        out[(size_t)T_LEN*NV + i]        = g_hN[i];
        out[(size_t)T_LEN*NV + 2*HD + i] = g_cN[i];
    }
}

// ---------------- launcher ----------------
extern "C" void kernel_launch(void* const* d_in, const int* in_sizes, int n_in,
                              void* d_out, int out_size) {
    const float* x   = (const float*)d_in[0];
    const float* h0  = (const float*)d_in[1];
    const float* c0  = (const float*)d_in[2];
    const float* Wih = (const float*)d_in[3];
    const float* Whh = (const float*)d_in[4];
    const float* bih = (const float*)d_in[5];
    const float* bhh = (const float*)d_in[6];
    const float* fcw = (const float*)d_in[7];
    const float* fcb = (const float*)d_in[8];
    float* out = (float*)d_out;
    (void)in_sizes; (void)n_in;

    cudaFuncSetAttribute(lstm_recur, cudaFuncAttributeMaxDynamicSharedMemorySize, SMEM_REC);

    cvt_inputs<<<2048, 256>>>(x, Wih, Whh, fcw);

    dim3 ggrid(G4/128, T_LEN/128);
    for (int l = 0; l < 2; ++l) {
        gemm_ih<<<ggrid, 256>>>(l, bih, bhh);
        init_recur<<<8, 256>>>(h0 + l*HD);
        lstm_recur<<<REC_CTAS, 448, SMEM_REC>>>(l, c0);
    }

    fc_logsoftmax<<<T_LEN, 128>>>(fcb, out);

    if (out_size >= T_LEN*NV + 4*HD)
        write_states<<<(2*HD + 255)/256, 256>>>(out);
}

// round 8
// speedup vs baseline: 1.3561x; 1.0878x over previous
#include <cuda_runtime.h>
#include <cuda_fp16.h>

#define T_LEN 2048
#define HD    2048
#define G4    8192
#define NV    128
#define WSZ   (8192ull*2048ull)
#define REC_CTAS 148
#define UNITS_SM 13
#define SMEM_REC (UNITS_SM*4*HD*2)      // weights only, bytes

// ---------------- device scratch ----------------
__device__ __half g_xh [(size_t)T_LEN*HD];
__device__ __half g_wih[2*WSZ];
__device__ __half g_whh[2*WSZ];
__device__ __half g_fcw[(size_t)NV*HD];
__device__ float  g_xg [(size_t)T_LEN*G4];   // layout [t][j][gate]
__device__ __half g_h1 [(size_t)T_LEN*HD];
__device__ __half g_h2 [(size_t)T_LEN*HD];
__device__ float  g_hN [2*HD];
__device__ float  g_cN [2*HD];
__device__ __align__(16) __half g_h0h[2][HD];
__device__ unsigned          g_cnt;          // reset per layer
__device__ volatile unsigned g_gen;          // reset per layer

// ---------------- fp32 -> fp16 conversion ----------------
__global__ void cvt_inputs(const float* __restrict__ x,
                           const float* __restrict__ wih,
                           const float* __restrict__ whh,
                           const float* __restrict__ fcw) {
    const size_t n = 2*WSZ;
    for (size_t i = (size_t)blockIdx.x*blockDim.x + threadIdx.x; i < n;
         i += (size_t)gridDim.x*blockDim.x) {
        g_wih[i] = __float2half(wih[i]);
        g_whh[i] = __float2half(whh[i]);
        if (i < (size_t)T_LEN*HD) g_xh[i]  = __float2half(x[i]);
        if (i < (size_t)NV*HD)    g_fcw[i] = __float2half(fcw[i]);
    }
}

// ---------------- HMMA GEMM: Xg = A @ W_ih^T + (b_ih + b_hh) ----------------
__device__ __forceinline__ void mma_16816(float d[4], const unsigned a[4], const unsigned b[2]) {
    asm volatile(
        "mma.sync.aligned.m16n8k16.row.col.f32.f16.f16.f32 "
        "{%0,%1,%2,%3}, {%4,%5,%6,%7}, {%8,%9}, {%0,%1,%2,%3};\n"
        : "+f"(d[0]), "+f"(d[1]), "+f"(d[2]), "+f"(d[3])
        : "r"(a[0]), "r"(a[1]), "r"(a[2]), "r"(a[3]), "r"(b[0]), "r"(b[1]));
}

__global__ void __launch_bounds__(256) gemm_ih(int layer,
                                               const float* __restrict__ bih_all,
                                               const float* __restrict__ bhh_all) {
    const __half* A = (layer == 0) ? g_xh : g_h1;
    const __half* B = g_wih + (size_t)layer*WSZ;
    const float*  bi = bih_all + layer*G4;
    const float*  bh = bhh_all + layer*G4;

    __shared__ __half As[128][40];
    __shared__ __half Bs[128][40];

    const int tid  = threadIdx.x;
    const int bn   = blockIdx.x * 128;
    const int bm   = blockIdx.y * 128;
    const int warp = tid >> 5, lane = tid & 31;
    const int wm = (warp >> 2) * 64, wn = (warp & 3) * 32;
    const int g = lane >> 2, tq = lane & 3;

    float acc[4][4][4];
    #pragma unroll
    for (int a = 0; a < 4; ++a)
        #pragma unroll
        for (int b = 0; b < 4; ++b)
            #pragma unroll
            for (int c = 0; c < 4; ++c) acc[a][b][c] = 0.f;

    for (int k0 = 0; k0 < HD; k0 += 32) {
        #pragma unroll
        for (int c = 0; c < 2; ++c) {
            int idx = tid + c*256;
            int r = idx >> 2, cc = (idx & 3) * 8;
            *(uint4*)&As[r][cc] = *(const uint4*)(A + (size_t)(bm + r)*HD + k0 + cc);
            *(uint4*)&Bs[r][cc] = *(const uint4*)(B + (size_t)(bn + r)*HD + k0 + cc);
        }
        __syncthreads();
        #pragma unroll
        for (int kk = 0; kk < 32; kk += 16) {
            unsigned af[4][4], bf[4][2];
            #pragma unroll
            for (int mt = 0; mt < 4; ++mt) {
                int r = wm + mt*16 + g;
                af[mt][0] = *(const unsigned*)&As[r  ][kk + 2*tq];
                af[mt][1] = *(const unsigned*)&As[r+8][kk + 2*tq];
                af[mt][2] = *(const unsigned*)&As[r  ][kk + 2*tq + 8];
                af[mt][3] = *(const unsigned*)&As[r+8][kk + 2*tq + 8];
            }
            #pragma unroll
            for (int nt = 0; nt < 4; ++nt) {
                int r = wn + nt*8 + g;
                bf[nt][0] = *(const unsigned*)&Bs[r][kk + 2*tq];
                bf[nt][1] = *(const unsigned*)&Bs[r][kk + 2*tq + 8];
            }
            #pragma unroll
            for (int mt = 0; mt < 4; ++mt)
                #pragma unroll
                for (int nt = 0; nt < 4; ++nt)
                    mma_16816(acc[mt][nt], af[mt], bf[nt]);
        }
        __syncthreads();
    }

    // Gate-interleaved epilogue: g_xg[row*G4 + j*4 + gate]
    #pragma unroll
    for (int mt = 0; mt < 4; ++mt) {
        #pragma unroll
        for (int nt = 0; nt < 4; ++nt) {
            int row = bm + wm + mt*16 + g;
            int col = bn + wn + nt*8 + 2*tq;
            int gate = col >> 11;
            int j    = col & 2047;
            float b0 = bi[col]   + bh[col];
            float b1 = bi[col+1] + bh[col+1];
            size_t i0  = (size_t)row*G4 + ((size_t)j << 2) + gate;
            size_t i08 = i0 + (size_t)8*G4;
            g_xg[i0]      = acc[mt][nt][0] + b0;
            g_xg[i0 + 4]  = acc[mt][nt][1] + b1;
            g_xg[i08]     = acc[mt][nt][2] + b0;
            g_xg[i08 + 4] = acc[mt][nt][3] + b1;
        }
    }
}

// ---------------- h0 conversion (both layers, once) ----------------
__global__ void init_h0(const float* __restrict__ h0) {
    int i = blockIdx.x*blockDim.x + threadIdx.x;
    if (i < 2*HD) g_h0h[i >> 11][i & 2047] = __float2half(h0[i]);
}

// ---------------- per-layer barrier reset ----------------
__global__ void reset_bar() {
    g_cnt = 0;
    g_gen = 0;
    __threadfence();
}

__device__ __forceinline__ float sigf(float x) { return 1.f / (1.f + __expf(-x)); }

__device__ __forceinline__ float hsum4(const __half2 s[4]) {
    float2 f0 = __half22float2(s[0]);
    float2 f1 = __half22float2(s[1]);
    float2 f2 = __half22float2(s[2]);
    float2 f3 = __half22float2(s[3]);
    return ((f0.x + f0.y) + (f1.x + f1.y)) + ((f2.x + f2.y) + (f3.x + f3.y));
}

// HFMA2 dot against register-resident h (hreg[8] uint4).
#define COMPUTE_DOTS_REG(W0, W1, W2, W3)                                       \
    do {                                                                       \
        _Pragma("unroll")                                                      \
        for (int k = 0; k < 4; ++k) { s0[k] = z; s1[k] = z; s2[k] = z; s3[k] = z; } \
        _Pragma("unroll")                                                      \
        for (int it = 0; it < 8; ++it) {                                       \
            const int col = it*256 + lane*8;                                   \
            uint4 v0 = *(const uint4*)((W0) + col);                            \
            uint4 v1 = *(const uint4*)((W1) + col);                            \
            uint4 v2 = *(const uint4*)((W2) + col);                            \
            uint4 v3 = *(const uint4*)((W3) + col);                            \
            const __half2* hp = (const __half2*)&hreg[it];                     \
            const __half2* p0 = (const __half2*)&v0;                           \
            const __half2* p1 = (const __half2*)&v1;                           \
            const __half2* p2 = (const __half2*)&v2;                           \
            const __half2* p3 = (const __half2*)&v3;                           \
            _Pragma("unroll")                                                  \
            for (int k = 0; k < 4; ++k) {                                      \
                s0[k] = __hfma2(p0[k], hp[k], s0[k]);                          \
                s1[k] = __hfma2(p1[k], hp[k], s1[k]);                          \
                s2[k] = __hfma2(p2[k], hp[k], s2[k]);                          \
                s3[k] = __hfma2(p3[k], hp[k], s3[k]);                          \
            }                                                                  \
        }                                                                      \
    } while (0)

// ---------------- persistent weight-stationary LSTM recurrence ----------------
__global__ void __launch_bounds__(448, 1) lstm_recur(int layer, const float* __restrict__ c0all) {
    extern __shared__ __half sm[];
    __half* ws = sm;                        // UNITS_SM * 4 * HD halfs

    const int tid  = threadIdx.x;
    const int lane = tid & 31;
    const int wrp  = tid >> 5;
    const int b    = blockIdx.x;
    const int nb   = (b < 124) ? 14 : 13;
    const int start = b*13 + min(b, 124);
    const int j    = start + wrp;
    const bool valid = (wrp < nb);

    const __half* Whh  = g_whh + (size_t)layer*WSZ;
    __half*       Hout = layer ? g_h2 : g_h1;

    // Stage 13 units' weights into smem once.
    {
        const int total = UNITS_SM*4*HD/8;
        for (int idx = tid; idx < total; idx += 448) {
            int u   = idx >> 10;
            int rem = idx & 1023;
            int g   = rem >> 8;
            int k   = (rem & 255) << 3;
            *(uint4*)(ws + ((size_t)(u*4 + g))*HD + k) =
                *(const uint4*)(Whh + (size_t)g*HD*HD + (size_t)(start + u)*HD + k);
        }
    }

    float c = valid ? c0all[layer*HD + j] : 0.f;

    const __half* gw0 = Whh + (size_t)j*HD;
    const __half* gw1 = gw0 + (size_t)HD*HD;
    const __half* gw2 = gw1 + (size_t)HD*HD;
    const __half* gw3 = gw2 + (size_t)HD*HD;

    __syncthreads();

    const __half2 z = __float2half2_rn(0.f);

    for (int t = 0; t < T_LEN; ++t) {
        // lane0 prefetch of input-gate vector (hidden behind the dot)
        float4 xv = make_float4(0.f, 0.f, 0.f, 0.f);
        if (valid && lane == 0)
            xv = __ldcg(((const float4*)(g_xg + (size_t)t*G4)) + j);

        // h_{t-1} -> registers: 8 MLP-overlapped 16B loads per thread
        const uint4* hp4 = (const uint4*)((t == 0) ? g_h0h[layer] : (Hout + (size_t)(t-1)*HD));
        uint4 hreg[8];
        #pragma unroll
        for (int it = 0; it < 8; ++it)
            hreg[it] = __ldcg(hp4 + it*32 + lane);

        __half2 s0[4], s1[4], s2[4], s3[4];
        if (valid) {
            if (wrp < UNITS_SM) {
                const __half* w0 = ws + (size_t)(wrp*4)*HD;
                COMPUTE_DOTS_REG(w0, w0 + HD, w0 + 2*HD, w0 + 3*HD);
            } else {
                COMPUTE_DOTS_REG(gw0, gw1, gw2, gw3);
            }
            float a0 = hsum4(s0), a1 = hsum4(s1), a2 = hsum4(s2), a3 = hsum4(s3);
            #pragma unroll
            for (int off = 16; off; off >>= 1) {
                a0 += __shfl_xor_sync(0xffffffffu, a0, off);
                a1 += __shfl_xor_sync(0xffffffffu, a1, off);
                a2 += __shfl_xor_sync(0xffffffffu, a2, off);
                a3 += __shfl_xor_sync(0xffffffffu, a3, off);
            }
            if (lane == 0) {
                float ig = sigf (a0 + xv.x);
                float fg = sigf (a1 + xv.y);
                float gg = tanhf(a2 + xv.z);
                float og = sigf (a3 + xv.w);
                c = fg * c + ig * gg;
                float h = og * tanhf(c);
                Hout[(size_t)t * HD + j] = __float2half(h);
                if (t == T_LEN - 1) { g_hN[layer*HD + j] = h; g_cN[layer*HD + j] = c; }
                __threadfence();                 // writer publishes its store
            }
        }

        if (t + 1 < T_LEN) {
            __syncthreads();                     // all warps stored + fenced
            if (tid == 0) {
                __threadfence();                 // cumulativity: order CTA's writes before arrive
                unsigned arrived = atomicAdd(&g_cnt, 1u) + 1u;
                unsigned target  = (unsigned)gridDim.x * (unsigned)(t + 1);
                if (arrived == target) {
                    g_gen = (unsigned)(t + 1);   // publish generation (volatile store)
                } else {
                    while (g_gen < (unsigned)(t + 1)) {}
                }
                __threadfence();                 // acquire before next step's reads
            }
            __syncthreads();
        }
    }
}

// ---------------- FC + log_softmax: one CTA per timestep ----------------
__global__ void __launch_bounds__(128) fc_logsoftmax(const float* __restrict__ fcb,
                                                     float* __restrict__ out) {
    const int t = blockIdx.x, v = threadIdx.x;
    __shared__ __align__(16) __half hsl[HD];
    __shared__ float lg[NV];
    __shared__ float red[NV];

    const uint4* src = (const uint4*)(g_h2 + (size_t)t * HD);
    ((uint4*)hsl)[v]       = src[v];
    ((uint4*)hsl)[v + 128] = src[v + 128];
    __syncthreads();

    float acc = fcb[v];
    const __half* wr = g_fcw + (size_t)v * HD;
    #pragma unroll 4
    for (int k = 0; k < HD; k += 8) {
        uint4 wv = *(const uint4*)(wr + k);
        uint4 hv = *(const uint4*)(hsl + k);
        float2 a, bb;
        a = __half22float2(*(const __half2*)&wv.x); bb = __half22float2(*(const __half2*)&hv.x); acc += a.x*bb.x + a.y*bb.y;
        a = __half22float2(*(const __half2*)&wv.y); bb = __half22float2(*(const __half2*)&hv.y); acc += a.x*bb.x + a.y*bb.y;
        a = __half22float2(*(const __half2*)&wv.z); bb = __half22float2(*(const __half2*)&hv.z); acc += a.x*bb.x + a.y*bb.y;
        a = __half22float2(*(const __half2*)&wv.w); bb = __half22float2(*(const __half2*)&hv.w); acc += a.x*bb.x + a.y*bb.y;
    }
    lg[v] = acc; red[v] = acc;
    __syncthreads();
    for (int s = 64; s > 0; s >>= 1) { if (v < s) red[v] = fmaxf(red[v], red[v + s]); __syncthreads(); }
    float mx = red[0];
    __syncthreads();
    red[v] = __expf(lg[v] - mx);
    __syncthreads();
    for (int s = 64; s > 0; s >>= 1) { if (v < s) red[v] += red[v + s]; __syncthreads(); }
    float lse = mx + logf(red[0]);
    out[(size_t)t * NV + v] = lg[v] - lse;
}

// ---------------- optional h_n / c_n tail ----------------
__global__ void write_states(float* __restrict__ out) {
    int i = blockIdx.x*blockDim.x + threadIdx.x;
    if (i < 2*HD) {
        out[(size_t)T_LEN*NV + i]        = g_hN[i];
        out[(size_t)T_LEN*NV + 2*HD + i] = g_cN[i];
    }
}

// ---------------- launcher ----------------
extern "C" void kernel_launch(void* const* d_in, const int* in_sizes, int n_in,
                              void* d_out, int out_size) {
    const float* x   = (const float*)d_in[0];
    const float* h0  = (const float*)d_in[1];
    const float* c0  = (const float*)d_in[2];
    const float* Wih = (const float*)d_in[3];
    const float* Whh = (const float*)d_in[4];
    const float* bih = (const float*)d_in[5];
    const float* bhh = (const float*)d_in[6];
    const float* fcw = (const float*)d_in[7];
    const float* fcb = (const float*)d_in[8];
    float* out = (float*)d_out;
    (void)in_sizes; (void)n_in;

    cudaFuncSetAttribute(lstm_recur, cudaFuncAttributeMaxDynamicSharedMemorySize, SMEM_REC);

    cvt_inputs<<<2048, 256>>>(x, Wih, Whh, fcw);
    init_h0<<<16, 256>>>(h0);

    dim3 ggrid(G4/128, T_LEN/128);
    for (int l = 0; l < 2; ++l) {
        gemm_ih<<<ggrid, 256>>>(l, bih, bhh);
        reset_bar<<<1, 1>>>();
        lstm_recur<<<REC_CTAS, 448, SMEM_REC>>>(l, c0);
    }

    fc_logsoftmax<<<T_LEN, 128>>>(fcb, out);

    if (out_size >= T_LEN*NV + 4*HD)
        write_states<<<(2*HD + 255)/256, 256>>>(out);
}

// round 10
// speedup vs baseline: 1.4615x; 1.0777x over previous
#include <cuda_runtime.h>
#include <cuda_fp16.h>

#define T_LEN 2048
#define HD    2048
#define G4    8192
#define NV    128
#define WSZ   (8192ull*2048ull)
#define REC_CTAS 148
#define UNITS_MAX 14
#define SMEM_REC (UNITS_MAX*4*HD*2)     // 229376 bytes: all weights smem-resident

// ---------------- device scratch ----------------
__device__ __half g_xh [(size_t)T_LEN*HD];
__device__ __half g_wih[2*WSZ];
__device__ __half g_whh[2*WSZ];
__device__ __half g_fcw[(size_t)NV*HD];
__device__ float  g_xg [(size_t)T_LEN*G4];   // layout [t][j][gate]
__device__ __half g_h1 [(size_t)T_LEN*HD];
__device__ __half g_h2 [(size_t)T_LEN*HD];
__device__ float  g_hN [2*HD];
__device__ float  g_cN [2*HD];
__device__ __align__(16) __half g_h0h[2][HD];
__device__ unsigned g_cnt;                   // cumulative across layers; reset per invocation

// ---------------- fp32 -> fp16 conversion (+ per-invocation barrier reset) ----------------
__global__ void cvt_inputs(const float* __restrict__ x,
                           const float* __restrict__ wih,
                           const float* __restrict__ whh,
                           const float* __restrict__ fcw) {
    if (blockIdx.x == 0 && threadIdx.x == 0) g_cnt = 0;   // stream-ordered before recurrence
    const size_t n = 2*WSZ;
    for (size_t i = (size_t)blockIdx.x*blockDim.x + threadIdx.x; i < n;
         i += (size_t)gridDim.x*blockDim.x) {
        g_wih[i] = __float2half(wih[i]);
        g_whh[i] = __float2half(whh[i]);
        if (i < (size_t)T_LEN*HD) g_xh[i]  = __float2half(x[i]);
        if (i < (size_t)NV*HD)    g_fcw[i] = __float2half(fcw[i]);
    }
}

// ---------------- HMMA GEMM: Xg = A @ W_ih^T + (b_ih + b_hh) ----------------
__device__ __forceinline__ void mma_16816(float d[4], const unsigned a[4], const unsigned b[2]) {
    asm volatile(
        "mma.sync.aligned.m16n8k16.row.col.f32.f16.f16.f32 "
        "{%0,%1,%2,%3}, {%4,%5,%6,%7}, {%8,%9}, {%0,%1,%2,%3};\n"
        : "+f"(d[0]), "+f"(d[1]), "+f"(d[2]), "+f"(d[3])
        : "r"(a[0]), "r"(a[1]), "r"(a[2]), "r"(a[3]), "r"(b[0]), "r"(b[1]));
}

__global__ void __launch_bounds__(256) gemm_ih(int layer,
                                               const float* __restrict__ bih_all,
                                               const float* __restrict__ bhh_all) {
    const __half* A = (layer == 0) ? g_xh : g_h1;
    const __half* B = g_wih + (size_t)layer*WSZ;
    const float*  bi = bih_all + layer*G4;
    const float*  bh = bhh_all + layer*G4;

    __shared__ __half As[128][40];
    __shared__ __half Bs[128][40];

    const int tid  = threadIdx.x;
    const int bn   = blockIdx.x * 128;
    const int bm   = blockIdx.y * 128;
    const int warp = tid >> 5, lane = tid & 31;
    const int wm = (warp >> 2) * 64, wn = (warp & 3) * 32;
    const int g = lane >> 2, tq = lane & 3;

    float acc[4][4][4];
    #pragma unroll
    for (int a = 0; a < 4; ++a)
        #pragma unroll
        for (int b = 0; b < 4; ++b)
            #pragma unroll
            for (int c = 0; c < 4; ++c) acc[a][b][c] = 0.f;

    for (int k0 = 0; k0 < HD; k0 += 32) {
        #pragma unroll
        for (int c = 0; c < 2; ++c) {
            int idx = tid + c*256;
            int r = idx >> 2, cc = (idx & 3) * 8;
            *(uint4*)&As[r][cc] = *(const uint4*)(A + (size_t)(bm + r)*HD + k0 + cc);
            *(uint4*)&Bs[r][cc] = *(const uint4*)(B + (size_t)(bn + r)*HD + k0 + cc);
        }
        __syncthreads();
        #pragma unroll
        for (int kk = 0; kk < 32; kk += 16) {
            unsigned af[4][4], bf[4][2];
            #pragma unroll
            for (int mt = 0; mt < 4; ++mt) {
                int r = wm + mt*16 + g;
                af[mt][0] = *(const unsigned*)&As[r  ][kk + 2*tq];
                af[mt][1] = *(const unsigned*)&As[r+8][kk + 2*tq];
                af[mt][2] = *(const unsigned*)&As[r  ][kk + 2*tq + 8];
                af[mt][3] = *(const unsigned*)&As[r+8][kk + 2*tq + 8];
            }
            #pragma unroll
            for (int nt = 0; nt < 4; ++nt) {
                int r = wn + nt*8 + g;
                bf[nt][0] = *(const unsigned*)&Bs[r][kk + 2*tq];
                bf[nt][1] = *(const unsigned*)&Bs[r][kk + 2*tq + 8];
            }
            #pragma unroll
            for (int mt = 0; mt < 4; ++mt)
                #pragma unroll
                for (int nt = 0; nt < 4; ++nt)
                    mma_16816(acc[mt][nt], af[mt], bf[nt]);
        }
        __syncthreads();
    }

    // Gate-interleaved epilogue: g_xg[row*G4 + j*4 + gate]
    #pragma unroll
    for (int mt = 0; mt < 4; ++mt) {
        #pragma unroll
        for (int nt = 0; nt < 4; ++nt) {
            int row = bm + wm + mt*16 + g;
            int col = bn + wn + nt*8 + 2*tq;
            int gate = col >> 11;
            int j    = col & 2047;
            float b0 = bi[col]   + bh[col];
            float b1 = bi[col+1] + bh[col+1];
            size_t i0  = (size_t)row*G4 + ((size_t)j << 2) + gate;
            size_t i08 = i0 + (size_t)8*G4;
            g_xg[i0]      = acc[mt][nt][0] + b0;
            g_xg[i0 + 4]  = acc[mt][nt][1] + b1;
            g_xg[i08]     = acc[mt][nt][2] + b0;
            g_xg[i08 + 4] = acc[mt][nt][3] + b1;
        }
    }
}

// ---------------- h0 conversion (both layers, once) ----------------
__global__ void init_h0(const float* __restrict__ h0) {
    int i = blockIdx.x*blockDim.x + threadIdx.x;
    if (i < 2*HD) g_h0h[i >> 11][i & 2047] = __float2half(h0[i]);
}

__device__ __forceinline__ float sigf(float x) { return 1.f / (1.f + __expf(-x)); }

// Fast, safe tanh: sign(x) * (1-e)/(1+e), e = exp(-2|x|) in (0,1]
__device__ __forceinline__ float tanhfast(float x) {
    float a = fabsf(x);
    float e = __expf(-2.f * a);
    float r = __fdividef(1.f - e, 1.f + e);
    return copysignf(r, x);
}

__device__ __forceinline__ float hsum4(const __half2 s[4]) {
    float2 f0 = __half22float2(s[0]);
    float2 f1 = __half22float2(s[1]);
    float2 f2 = __half22float2(s[2]);
    float2 f3 = __half22float2(s[3]);
    return ((f0.x + f0.y) + (f1.x + f1.y)) + ((f2.x + f2.y) + (f3.x + f3.y));
}

// HFMA2 dot against register-resident h (hreg[8] uint4), weights from SMEM.
#define COMPUTE_DOTS_REG(W0, W1, W2, W3)                                       \
    do {                                                                       \
        _Pragma("unroll")                                                      \
        for (int k = 0; k < 4; ++k) { s0[k] = z; s1[k] = z; s2[k] = z; s3[k] = z; } \
        _Pragma("unroll")                                                      \
        for (int it = 0; it < 8; ++it) {                                       \
            const int col = it*256 + lane*8;                                   \
            uint4 v0 = *(const uint4*)((W0) + col);                            \
            uint4 v1 = *(const uint4*)((W1) + col);                            \
            uint4 v2 = *(const uint4*)((W2) + col);                            \
            uint4 v3 = *(const uint4*)((W3) + col);                            \
            const __half2* hp = (const __half2*)&hreg[it];                     \
            const __half2* p0 = (const __half2*)&v0;                           \
            const __half2* p1 = (const __half2*)&v1;                           \
            const __half2* p2 = (const __half2*)&v2;                           \
            const __half2* p3 = (const __half2*)&v3;                           \
            _Pragma("unroll")                                                  \
            for (int k = 0; k < 4; ++k) {                                      \
                s0[k] = __hfma2(p0[k], hp[k], s0[k]);                          \
                s1[k] = __hfma2(p1[k], hp[k], s1[k]);                          \
                s2[k] = __hfma2(p2[k], hp[k], s2[k]);                          \
                s3[k] = __hfma2(p3[k], hp[k], s3[k]);                          \
            }                                                                  \
        }                                                                      \
    } while (0)

// ---------------- persistent weight-stationary LSTM recurrence ----------------
// 148 CTAs; CTA b owns nb = 14 (b<124) or 13 units — ALL weights in SMEM.
__global__ void __launch_bounds__(448, 1) lstm_recur(int layer, const float* __restrict__ c0all) {
    extern __shared__ __half ws[];          // up to 14 * 4 * HD halfs

    const int tid  = threadIdx.x;
    const int lane = tid & 31;
    const int wrp  = tid >> 5;
    const int b    = blockIdx.x;
    const int nb   = (b < 124) ? 14 : 13;
    const int start = b*13 + min(b, 124);
    const int j    = start + wrp;
    const bool valid = (wrp < nb);

    const __half* Whh  = g_whh + (size_t)layer*WSZ;
    __half*       Hout = layer ? g_h2 : g_h1;

    // Stage ALL nb units' weights into smem once per layer launch.
    {
        const int totq = nb << 10;          // nb*4*2048/8 uint4
        for (int idx = tid; idx < totq; idx += 448) {
            int u   = idx >> 10;
            int rem = idx & 1023;
            int g   = rem >> 8;
            int k   = (rem & 255) << 3;
            *(uint4*)(ws + ((size_t)(u*4 + g))*HD + k) =
                *(const uint4*)(Whh + (size_t)g*HD*HD + (size_t)(start + u)*HD + k);
        }
    }

    float c = valid ? c0all[layer*HD + j] : 0.f;

    __syncthreads();

    const __half2 z = __float2half2_rn(0.f);
    // Cumulative counter: layer 0 arrivals cover t=0..2046, layer 1 continues.
    const unsigned base = (unsigned)layer * (unsigned)(T_LEN - 1) * (unsigned)REC_CTAS;

    for (int t = 0; t < T_LEN; ++t) {
        // lane0 prefetch of input-gate vector (hidden behind the dot)
        float4 xv = make_float4(0.f, 0.f, 0.f, 0.f);
        if (valid && lane == 0)
            xv = __ldcg(((const float4*)(g_xg + (size_t)t*G4)) + j);

        // h_{t-1} -> registers: 8 MLP-overlapped 16B loads per thread
        const uint4* hp4 = (const uint4*)((t == 0) ? g_h0h[layer] : (Hout + (size_t)(t-1)*HD));
        uint4 hreg[8];
        #pragma unroll
        for (int it = 0; it < 8; ++it)
            hreg[it] = __ldcg(hp4 + it*32 + lane);

        __half2 s0[4], s1[4], s2[4], s3[4];
        if (valid) {
            const __half* w0 = ws + (size_t)(wrp*4)*HD;
            COMPUTE_DOTS_REG(w0, w0 + HD, w0 + 2*HD, w0 + 3*HD);
            float a0 = hsum4(s0), a1 = hsum4(s1), a2 = hsum4(s2), a3 = hsum4(s3);
            #pragma unroll
            for (int off = 16; off; off >>= 1) {
                a0 += __shfl_xor_sync(0xffffffffu, a0, off);
                a1 += __shfl_xor_sync(0xffffffffu, a1, off);
                a2 += __shfl_xor_sync(0xffffffffu, a2, off);
                a3 += __shfl_xor_sync(0xffffffffu, a3, off);
            }
            if (lane == 0) {
                float ig = sigf    (a0 + xv.x);
                float fg = sigf    (a1 + xv.y);
                float gg = tanhfast(a2 + xv.z);
                float og = sigf    (a3 + xv.w);
                c = fg * c + ig * gg;
                float h = og * tanhfast(c);
                Hout[(size_t)t * HD + j] = __float2half(h);
                if (t == T_LEN - 1) { g_hN[layer*HD + j] = h; g_cN[layer*HD + j] = c; }
                __threadfence();                 // writer publishes its store
            }
        }

        if (t + 1 < T_LEN) {
            __syncthreads();                     // all warps stored + fenced
            if (tid == 0) {
                __threadfence();                 // release (CG grid.sync pattern)
                atomicAdd(&g_cnt, 1u);           // arrive (strong)
                const unsigned target = base + (unsigned)REC_CTAS * (unsigned)(t + 1);
                volatile unsigned* vc = &g_cnt;  // STRONG poll — volatile load synchronizes
                while (*vc < target) {}
                __threadfence();                 // acquire before next step's reads
            }
            __syncthreads();
        }
    }
}

// ---------------- FC + log_softmax: one CTA per timestep ----------------
__global__ void __launch_bounds__(128) fc_logsoftmax(const float* __restrict__ fcb,
                                                     float* __restrict__ out) {
    const int t = blockIdx.x, v = threadIdx.x;
    __shared__ __align__(16) __half hsl[HD];
    __shared__ float lg[NV];
    __shared__ float red[NV];

    const uint4* src = (const uint4*)(g_h2 + (size_t)t * HD);
    ((uint4*)hsl)[v]       = src[v];
    ((uint4*)hsl)[v + 128] = src[v + 128];
    __syncthreads();

    float acc = fcb[v];
    const __half* wr = g_fcw + (size_t)v * HD;
    #pragma unroll 4
    for (int k = 0; k < HD; k += 8) {
        uint4 wv = *(const uint4*)(wr + k);
        uint4 hv = *(const uint4*)(hsl + k);
        float2 a, bb;
        a = __half22float2(*(const __half2*)&wv.x); bb = __half22float2(*(const __half2*)&hv.x); acc += a.x*bb.x + a.y*bb.y;
        a = __half22float2(*(const __half2*)&wv.y); bb = __half22float2(*(const __half2*)&hv.y); acc += a.x*bb.x + a.y*bb.y;
        a = __half22float2(*(const __half2*)&wv.z); bb = __half22float2(*(const __half2*)&hv.z); acc += a.x*bb.x + a.y*bb.y;
        a = __half22float2(*(const __half2*)&wv.w); bb = __half22float2(*(const __half2*)&hv.w); acc += a.x*bb.x + a.y*bb.y;
    }
    lg[v] = acc; red[v] = acc;
    __syncthreads();
    for (int s = 64; s > 0; s >>= 1) { if (v < s) red[v] = fmaxf(red[v], red[v + s]); __syncthreads(); }
    float mx = red[0];
    __syncthreads();
    red[v] = __expf(lg[v] - mx);
    __syncthreads();
    for (int s = 64; s > 0; s >>= 1) { if (v < s) red[v] += red[v + s]; __syncthreads(); }
    float lse = mx + logf(red[0]);
    out[(size_t)t * NV + v] = lg[v] - lse;
}

// ---------------- optional h_n / c_n tail ----------------
__global__ void write_states(float* __restrict__ out) {
    int i = blockIdx.x*blockDim.x + threadIdx.x;
    if (i < 2*HD) {
        out[(size_t)T_LEN*NV + i]        = g_hN[i];
        out[(size_t)T_LEN*NV + 2*HD + i] = g_cN[i];
    }
}

// ---------------- launcher ----------------
extern "C" void kernel_launch(void* const* d_in, const int* in_sizes, int n_in,
                              void* d_out, int out_size) {
    const float* x   = (const float*)d_in[0];
    const float* h0  = (const float*)d_in[1];
    const float* c0  = (const float*)d_in[2];
    const float* Wih = (const float*)d_in[3];
    const float* Whh = (const float*)d_in[4];
    const float* bih = (const float*)d_in[5];
    const float* bhh = (const float*)d_in[6];
    const float* fcw = (const float*)d_in[7];
    const float* fcb = (const float*)d_in[8];
    float* out = (float*)d_out;
    (void)in_sizes; (void)n_in;

    cudaFuncSetAttribute(lstm_recur, cudaFuncAttributeMaxDynamicSharedMemorySize, SMEM_REC);

    cvt_inputs<<<2048, 256>>>(x, Wih, Whh, fcw);
    init_h0<<<16, 256>>>(h0);

    dim3 ggrid(G4/128, T_LEN/128);
    for (int l = 0; l < 2; ++l) {
        gemm_ih<<<ggrid, 256>>>(l, bih, bhh);
        lstm_recur<<<REC_CTAS, 448, SMEM_REC>>>(l, c0);
    }

    fc_logsoftmax<<<T_LEN, 128>>>(fcb, out);

    if (out_size >= T_LEN*NV + 4*HD)
        write_states<<<(2*HD + 255)/256, 256>>>(out);
}